// round 15
// baseline (speedup 1.0000x reference)
#include <cuda_runtime.h>
#include <cuda_bf16.h>
#include <cstdint>

#define DD 16
#define LL 6
#define KK 64
#define BLOCK 256
#define TILE_M 256

typedef unsigned long long u64;
typedef unsigned int u32;

#define C1_        (-7.2134752044448169f)   /* -5 * log2(e)          */
#define C2SCALE_   (-14.426950408889634f)   /* -10 * log2(e)         */
#define PI_        3.14159265358979323846f
#define HALF_PI_   1.5707963267948966f
#define LN2_TENTH  0.069314718055994531f    /* 0.1 * ln(2)           */
#define QUARTER_PI2 2.4674011002723397f     /* (pi/2)^2              */

// A&S 4.4.45 deg-3 rebased in u = 1-a:  p~(u) = p(1-u)
#define PT0  1.4141461f
#define PT1  0.1197803f
#define PT2  0.0180731f
#define PT3  0.0187293f

// B operand, lane-permuted: [384 comps][16 u32]; word 4*t+j = lane t's uint4
// = (mh_t, mh_{t+4}, ml_t, ml_{t+4})  -> one LDS.128 per lane per component-tile
__device__ u32   g_B[LL * KK][16];
__device__ float g_W[LL * KK];   // 2^(C2SCALE*alpha + C1*pi^2/4)
__device__ float g_wv[LL];

__device__ __forceinline__ u32 pack_bf16x2(float a, float b) {
    __nv_bfloat162 h = __floats2bfloat162_rn(a, b);
    return *reinterpret_cast<u32*>(&h);
}

// ------------------------------------------------------------------ prep
__global__ void prep_kernel(const float* __restrict__ mus,
                            const float* __restrict__ alphas,
                            const float* __restrict__ ws) {
    int tid = threadIdx.x;
    if (tid < LL) {
        float w = ws[tid];
        g_wv[tid] = expf(-w * w);
    }
    if (tid >= LL * KK) return;
    int l = tid >> 6;
    int k = tid & 63;
    const float* m = mus + l * DD * KK + k;   // [L, D, K]
    float v[DD];
    float s = 0.f;
#pragma unroll
    for (int d = 0; d < DD; d++) {
        v[d] = m[d * KK];
        s += v[d] * v[d];
    }
    float inv = 1.0f / sqrtf(s);
#pragma unroll
    for (int d = 0; d < DD; d++) v[d] *= inv;
    u32 mh[8], ml[8];
#pragma unroll
    for (int i = 0; i < 8; i++) {
        float a = v[2 * i], b = v[2 * i + 1];
        __nv_bfloat162 hb = __floats2bfloat162_rn(a, b);
        float ra = a - __bfloat162float(hb.x);
        float rb = b - __bfloat162float(hb.y);
        mh[i] = *reinterpret_cast<u32*>(&hb);
        ml[i] = pack_bf16x2(ra, rb);
    }
    // permuted store: lane t's uint4 = (mh[t], mh[t+4], ml[t], ml[t+4])
#pragma unroll
    for (int t = 0; t < 4; t++) {
        g_B[tid][4 * t + 0] = mh[t];
        g_B[tid][4 * t + 1] = mh[t + 4];
        g_B[tid][4 * t + 2] = ml[t];
        g_B[tid][4 * t + 3] = ml[t + 4];
    }
    g_W[tid] = exp2f(C2SCALE_ * alphas[tid] + C1_ * QUARTER_PI2);
}

// ---------------------------------------------------------------- helpers
__device__ __forceinline__ float fast_sqrt(float x) {
    float r; asm("sqrt.approx.f32 %0, %1;" : "=f"(r) : "f"(x)); return r;
}
__device__ __forceinline__ float fast_ex2(float x) {
    float r; asm("ex2.approx.f32 %0, %1;" : "=f"(r) : "f"(x)); return r;
}
__device__ __forceinline__ float fast_lg2(float x) {
    float r; asm("lg2.approx.f32 %0, %1;" : "=f"(r) : "f"(x)); return r;
}

// m16n8k16 row.col bf16 -> f32 accumulate (plain PTX, valid on compute_103)
__device__ __forceinline__ void mma16816(float& d0, float& d1, float& d2, float& d3,
                                         u32 a0, u32 a1, u32 a2, u32 a3,
                                         u32 b0, u32 b1) {
    asm volatile(
        "mma.sync.aligned.m16n8k16.row.col.f32.bf16.bf16.f32 "
        "{%0,%1,%2,%3}, {%4,%5,%6,%7}, {%8,%9}, {%0,%1,%2,%3};"
        : "+f"(d0), "+f"(d1), "+f"(d2), "+f"(d3)
        : "r"(a0), "r"(a1), "r"(a2), "r"(a3), "r"(b0), "r"(b1));
}

// hi/lo bf16 split of a float2 (identical math to the verified staging path)
__device__ __forceinline__ void split2(float2 f, u32& hi, u32& lo) {
    __nv_bfloat162 hb = __floats2bfloat162_rn(f.x, f.y);
    float rx = f.x - __bfloat162float(hb.x);
    float ry = f.y - __bfloat162float(hb.y);
    hi = *reinterpret_cast<u32*>(&hb);
    lo = pack_bf16x2(rx, ry);
}

// epilogue core (deg-3 A&S rebased in u = 1-|t|, W-multiplicative alpha):
//   acos(|t|) = sqrt(u) * p~(u);  c = copysign(pi/2 - acos, t)
//   term = W * 2^(C1*c^2 - C1*pi*c)    [C1*pi^2/4 folded into W]
__device__ __forceinline__ float ep_term(float dot, float W) {
    float u = fmaxf(1.0f - fabsf(dot), 0.0f);   // NaN guard for sqrt
    float s = fast_sqrt(u);
    float p = fmaf(fmaf(fmaf(PT3, u, PT2), u, PT1), u, PT0);
    float dp = s * p;                           // acos(|dot|)
    float c = copysignf(HALF_PI_ - dp, dot);
    float arg = fmaf(C1_, c, -(C1_) * PI_) * c; // C1*c^2 - C1*pi*c
    return W * fast_ex2(arg);
}

// ------------------------------------------------------------------ main
__global__ __launch_bounds__(BLOCK, 6)
void main_kernel(const float* __restrict__ xs,
                 float* __restrict__ out,
                 int n_total) {
    __shared__ uint4  sB4[LL * KK * 4];      // 24.0 KB permuted B (uint4/lane)
    __shared__ float2 sW[LL * 32];           // 1.5 KB W pairs
    __shared__ float  sWV[LL];

    const int tid = threadIdx.x;
    {
        const float2* gw = reinterpret_cast<const float2*>(g_W);
        for (int i = tid; i < LL * 32; i += BLOCK) sW[i] = gw[i];
        if (tid < LL) sWV[tid] = g_wv[tid];
        const uint4* gb = reinterpret_cast<const uint4*>(&g_B[0][0]);
#pragma unroll
        for (int i = tid; i < LL * KK * 4; i += BLOCK) sB4[i] = gb[i];
    }
    __syncthreads();

    const int wid = tid >> 5;
    const int lane = tid & 31;
    const int gid = lane >> 2;   // quad row id 0..7 (also component-in-tile)
    const int tig = lane & 3;    // thread-in-group

    const float2* xp2 = reinterpret_cast<const float2*>(xs);

    // mt OUTER loop (reg diet); nt fully unrolled inside
#pragma unroll 1
    for (int mt = 0; mt < 2; mt++) {
        // A fragments directly from gmem (no smem staging):
        // rows r0 and r0+8, float2 word pairs tig and tig+4
        const int r0 = blockIdx.x * TILE_M + wid * 32 + mt * 16 + gid;
        const int rA = (r0 < n_total) ? r0 : (n_total - 1);
        const int rB = (r0 + 8 < n_total) ? (r0 + 8) : (n_total - 1);
        u32 ah0, ah1, ah2, ah3, al0, al1, al2, al3;
        split2(xp2[(size_t)rA * 8 + tig],     ah0, al0);
        split2(xp2[(size_t)rB * 8 + tig],     ah1, al1);
        split2(xp2[(size_t)rA * 8 + tig + 4], ah2, al2);
        split2(xp2[(size_t)rB * 8 + tig + 4], ah3, al3);

        float F0 = 0.f, F1 = 0.f;
#pragma unroll 1
        for (int l = 0; l < LL; l++) {
            // base pointers for this layer: immediate offsets per nt
            const uint4*  bp = sB4 + (l * 64 + gid) * 4 + tig;
            const float2* cp = sW + l * 32 + tig;
            float sum0 = 0.f, sum1 = 0.f;
#pragma unroll
            for (int nt = 0; nt < 8; nt++) {
                uint4  bv = bp[nt * 32];     // (bh0, bh1, bl0, bl1): 1 LDS.128
                float2 ww = cp[nt * 4];

                float acc0 = 0.f, acc1 = 0.f, acc2 = 0.f, acc3 = 0.f;
                mma16816(acc0, acc1, acc2, acc3, ah0, ah1, ah2, ah3, bv.x, bv.y);
                mma16816(acc0, acc1, acc2, acc3, ah0, ah1, ah2, ah3, bv.z, bv.w);
                mma16816(acc0, acc1, acc2, acc3, al0, al1, al2, al3, bv.x, bv.y);

                sum0 += ep_term(acc0, ww.x);
                sum0 += ep_term(acc1, ww.y);
                sum1 += ep_term(acc2, ww.x);
                sum1 += ep_term(acc3, ww.y);
            }

            sum0 += __shfl_xor_sync(0xFFFFFFFFu, sum0, 1);
            sum0 += __shfl_xor_sync(0xFFFFFFFFu, sum0, 2);
            sum1 += __shfl_xor_sync(0xFFFFFFFFu, sum1, 1);
            sum1 += __shfl_xor_sync(0xFFFFFFFFu, sum1, 2);

            float w = sWV[l];
            float mc0 = LN2_TENTH * fast_lg2(sum0);
            float mc1 = LN2_TENTH * fast_lg2(sum1);
            F0 = fmaf(w, fmaxf(F0, 0.f), (1.0f - w) * mc0);
            F1 = fmaf(w, fmaxf(F1, 0.f), (1.0f - w) * mc1);
        }

        // ---- store this m-tile: lane tig==0 of each quad writes 2 points ----
        if (tig == 0) {
            if (r0 < n_total)
                out[r0] = 0.1f * log1pf(fast_ex2(C2SCALE_ * F0));
            if (r0 + 8 < n_total)
                out[r0 + 8] = 0.1f * log1pf(fast_ex2(C2SCALE_ * F1));
        }
    }
}

extern "C" void kernel_launch(void* const* d_in, const int* in_sizes, int n_in,
                              void* d_out, int out_size) {
    const float* xs     = (const float*)d_in[0];
    const float* mus    = (const float*)d_in[1];
    const float* alphas = (const float*)d_in[2];
    const float* ws     = (const float*)d_in[3];
    float* out = (float*)d_out;

    int n_total = in_sizes[0] / DD;

    prep_kernel<<<1, LL * KK>>>(mus, alphas, ws);
    int blocks = (n_total + TILE_M - 1) / TILE_M;
    main_kernel<<<blocks, BLOCK>>>(xs, out, n_total);
}

// round 16
// speedup vs baseline: 1.1655x; 1.1655x over previous
#include <cuda_runtime.h>
#include <cuda_bf16.h>
#include <cuda_fp16.h>
#include <cstdint>

#define DD 16
#define LL 6
#define KK 64
#define BLOCK 256
#define TILE_M 256

typedef unsigned long long u64;
typedef unsigned int u32;

#define C1_        (-7.2134752044448169f)   /* -5 * log2(e)          */
#define C2SCALE_   (-14.426950408889634f)   /* -10 * log2(e)         */
#define PI_        3.14159265358979323846f
#define HALF_PI_   1.5707963267948966f
#define LN2_TENTH  0.069314718055994531f    /* 0.1 * ln(2)           */
#define QUARTER_PI2 2.4674011002723397f     /* (pi/2)^2              */

// A&S 4.4.45 deg-3 rebased in u = 1-a:  p~(u) = p(1-u)
#define PT0  1.4141461f
#define PT1  0.1197803f
#define PT2  0.0180731f
#define PT3  0.0187293f

// B operand fp16, lane-permuted: [384 comps][8 u32];
// words [2t, 2t+1] = (pair_t, pair_{t+4}) -> lane t reads one uint2 (LDS.64)
__device__ u32   g_B[LL * KK][8];
__device__ float g_W[LL * KK];   // 2^(C2SCALE*alpha + C1*pi^2/4)
__device__ float g_wv[LL];

__device__ __forceinline__ u32 pack_h2(float a, float b) {
    __half2 h = __floats2half2_rn(a, b);
    return *reinterpret_cast<u32*>(&h);
}

// ------------------------------------------------------------------ prep
__global__ void prep_kernel(const float* __restrict__ mus,
                            const float* __restrict__ alphas,
                            const float* __restrict__ ws) {
    int tid = threadIdx.x;
    if (tid < LL) {
        float w = ws[tid];
        g_wv[tid] = expf(-w * w);
    }
    if (tid >= LL * KK) return;
    int l = tid >> 6;
    int k = tid & 63;
    const float* m = mus + l * DD * KK + k;   // [L, D, K]
    float v[DD];
    float s = 0.f;
#pragma unroll
    for (int d = 0; d < DD; d++) {
        v[d] = m[d * KK];
        s += v[d] * v[d];
    }
    float inv = 1.0f / sqrtf(s);
#pragma unroll
    for (int d = 0; d < DD; d++) v[d] *= inv;
    u32 mp[8];
#pragma unroll
    for (int i = 0; i < 8; i++) mp[i] = pack_h2(v[2 * i], v[2 * i + 1]);
    // permuted: lane t's uint2 = (mp[t], mp[t+4])
#pragma unroll
    for (int t = 0; t < 4; t++) {
        g_B[tid][2 * t + 0] = mp[t];
        g_B[tid][2 * t + 1] = mp[t + 4];
    }
    g_W[tid] = exp2f(C2SCALE_ * alphas[tid] + C1_ * QUARTER_PI2);
}

// ---------------------------------------------------------------- helpers
__device__ __forceinline__ float fast_sqrt(float x) {
    float r; asm("sqrt.approx.f32 %0, %1;" : "=f"(r) : "f"(x)); return r;
}
__device__ __forceinline__ float fast_ex2(float x) {
    float r; asm("ex2.approx.f32 %0, %1;" : "=f"(r) : "f"(x)); return r;
}
__device__ __forceinline__ float fast_lg2(float x) {
    float r; asm("lg2.approx.f32 %0, %1;" : "=f"(r) : "f"(x)); return r;
}

// m16n8k16 row.col fp16 -> f32 accumulate (plain PTX, valid on compute_103)
__device__ __forceinline__ void mma16816h(float& d0, float& d1, float& d2, float& d3,
                                          u32 a0, u32 a1, u32 a2, u32 a3,
                                          u32 b0, u32 b1) {
    asm volatile(
        "mma.sync.aligned.m16n8k16.row.col.f32.f16.f16.f32 "
        "{%0,%1,%2,%3}, {%4,%5,%6,%7}, {%8,%9}, {%0,%1,%2,%3};"
        : "+f"(d0), "+f"(d1), "+f"(d2), "+f"(d3)
        : "r"(a0), "r"(a1), "r"(a2), "r"(a3), "r"(b0), "r"(b1));
}

// epilogue core (deg-3 A&S rebased in u = 1-|t|, W-multiplicative alpha):
//   acos(|t|) = sqrt(u) * p~(u);  c = copysign(pi/2 - acos, t)
//   term = W * 2^(C1*c^2 - C1*pi*c)    [C1*pi^2/4 folded into W]
__device__ __forceinline__ float ep_term(float dot, float W) {
    float u = fmaxf(1.0f - fabsf(dot), 0.0f);   // NaN guard for sqrt
    float s = fast_sqrt(u);
    float p = fmaf(fmaf(fmaf(PT3, u, PT2), u, PT1), u, PT0);
    float dp = s * p;                           // acos(|dot|)
    float c = copysignf(HALF_PI_ - dp, dot);
    float arg = fmaf(C1_, c, -(C1_) * PI_) * c; // C1*c^2 - C1*pi*c
    return W * fast_ex2(arg);
}

// ------------------------------------------------------------------ main
__global__ __launch_bounds__(BLOCK, 6)
void main_kernel(const float* __restrict__ xs,
                 float* __restrict__ out,
                 int n_total) {
    __shared__ u32    sA[TILE_M][9];         // 9.2 KB fp16 x (8 pairs + pad)
    __shared__ uint2  sB2[LL * KK * 4];      // 12.0 KB permuted fp16 B
    __shared__ float2 sW[LL * 32];           // 1.5 KB W pairs
    __shared__ float  sWV[LL];

    const int tid = threadIdx.x;
    {
        const float2* gw = reinterpret_cast<const float2*>(g_W);
        for (int i = tid; i < LL * 32; i += BLOCK) sW[i] = gw[i];
        if (tid < LL) sWV[tid] = g_wv[tid];
        const uint4* gb = reinterpret_cast<const uint4*>(&g_B[0][0]);
        uint4* sb = reinterpret_cast<uint4*>(sB2);
#pragma unroll
        for (int i = tid; i < LL * KK * 2; i += BLOCK) sb[i] = gb[i];  // 768 uint4
    }

    // ---- build A rows (fp16): thread tid owns point blockIdx*256 + tid ----
    int n0 = blockIdx.x * TILE_M + tid;
    int n_c = (n0 < n_total) ? n0 : (n_total - 1);
    {
        const float4* xv = reinterpret_cast<const float4*>(xs + (size_t)n_c * DD);
        float4 v0 = xv[0], v1 = xv[1], v2 = xv[2], v3 = xv[3];
        sA[tid][0] = pack_h2(v0.x, v0.y);
        sA[tid][1] = pack_h2(v0.z, v0.w);
        sA[tid][2] = pack_h2(v1.x, v1.y);
        sA[tid][3] = pack_h2(v1.z, v1.w);
        sA[tid][4] = pack_h2(v2.x, v2.y);
        sA[tid][5] = pack_h2(v2.z, v2.w);
        sA[tid][6] = pack_h2(v3.x, v3.y);
        sA[tid][7] = pack_h2(v3.z, v3.w);
    }
    __syncthreads();

    const int wid = tid >> 5;
    const int lane = tid & 31;
    const int gid = lane >> 2;   // quad row id 0..7 (also component-in-tile)
    const int tig = lane & 3;    // thread-in-group

    // mt OUTER loop (reg diet); nt fully unrolled inside
#pragma unroll 1
    for (int mt = 0; mt < 2; mt++) {
        const int r0 = wid * 32 + mt * 16 + gid;
        u32 a0 = sA[r0][tig];
        u32 a1 = sA[r0 + 8][tig];
        u32 a2 = sA[r0][tig + 4];
        u32 a3 = sA[r0 + 8][tig + 4];

        float F0 = 0.f, F1 = 0.f;
#pragma unroll 1
        for (int l = 0; l < LL; l++) {
            const uint2*  bp = sB2 + (l * 64 + gid) * 4 + tig;
            const float2* cp = sW + l * 32 + tig;
            float sum0 = 0.f, sum1 = 0.f;
#pragma unroll
            for (int nt = 0; nt < 8; nt++) {
                uint2  bv = bp[nt * 32];     // (b0, b1): one LDS.64
                float2 ww = cp[nt * 4];

                float acc0 = 0.f, acc1 = 0.f, acc2 = 0.f, acc3 = 0.f;
                mma16816h(acc0, acc1, acc2, acc3, a0, a1, a2, a3, bv.x, bv.y);

                sum0 += ep_term(acc0, ww.x);
                sum0 += ep_term(acc1, ww.y);
                sum1 += ep_term(acc2, ww.x);
                sum1 += ep_term(acc3, ww.y);
            }

            sum0 += __shfl_xor_sync(0xFFFFFFFFu, sum0, 1);
            sum0 += __shfl_xor_sync(0xFFFFFFFFu, sum0, 2);
            sum1 += __shfl_xor_sync(0xFFFFFFFFu, sum1, 1);
            sum1 += __shfl_xor_sync(0xFFFFFFFFu, sum1, 2);

            float w = sWV[l];
            float mc0 = LN2_TENTH * fast_lg2(sum0);
            float mc1 = LN2_TENTH * fast_lg2(sum1);
            F0 = fmaf(w, fmaxf(F0, 0.f), (1.0f - w) * mc0);
            F1 = fmaf(w, fmaxf(F1, 0.f), (1.0f - w) * mc1);
        }

        // ---- store this m-tile: lane tig==0 of each quad writes 2 points ----
        if (tig == 0) {
            int p0 = blockIdx.x * TILE_M + r0;
            if (p0 < n_total)
                out[p0] = 0.1f * log1pf(fast_ex2(C2SCALE_ * F0));
            if (p0 + 8 < n_total)
                out[p0 + 8] = 0.1f * log1pf(fast_ex2(C2SCALE_ * F1));
        }
    }
}

extern "C" void kernel_launch(void* const* d_in, const int* in_sizes, int n_in,
                              void* d_out, int out_size) {
    const float* xs     = (const float*)d_in[0];
    const float* mus    = (const float*)d_in[1];
    const float* alphas = (const float*)d_in[2];
    const float* ws     = (const float*)d_in[3];
    float* out = (float*)d_out;

    int n_total = in_sizes[0] / DD;

    prep_kernel<<<1, LL * KK>>>(mus, alphas, ws);
    int blocks = (n_total + TILE_M - 1) / TILE_M;
    main_kernel<<<blocks, BLOCK>>>(xs, out, n_total);
}